// round 9
// baseline (speedup 1.0000x reference)
#include <cuda_runtime.h>
#include <cuda_bf16.h>
#include <cstdint>

// out[n,0,p] = -sqrt(max(||e_n||^2 + ||p_p||^2 - 2 e_n.p_p, 1e-12))
// N=500000, P=256, D=128.  sm_103 HMMA (bf16 mma.sync) path.
// R8 structure (512 thr, 16 warps 4Mx4N, 1 CTA/SM, B resident+permuted,
// A double-buffered, float4 STG epilogue) + barrier moved BEFORE the
// epilogue so epilogue(i) overlaps GEMM(i+1) across warps.

static constexpr int kD = 128;
static constexpr int kP = 256;
static constexpr int kTM = 128;          // embedding rows per tile
static constexpr int kThreads = 512;     // 16 warps: 4 (M) x 4 (N)

static constexpr uint32_t ROWB = 272;    // bf16 row: 256B + 16B pad (conflict-free ldsm)
static constexpr uint32_t OFF_E2 = 0;                        // 2 x 128 f32
static constexpr uint32_t OFF_P2 = 1024;                     // 256 f32
static constexpr uint32_t OFF_A  = 2048;                     // 2 x 128 x ROWB
static constexpr uint32_t A_BUF  = 128u * ROWB;              // 34816
static constexpr uint32_t OFF_B  = OFF_A + 2u * A_BUF;       // 71680
static constexpr uint32_t SMEM_TOTAL = OFF_B + 256u * ROWB;  // 141312

__device__ __forceinline__ uint32_t smem_u32(const void* p) {
    uint32_t a;
    asm("{ .reg .u64 t; cvta.to.shared.u64 t, %1; cvt.u32.u64 %0, t; }" : "=r"(a) : "l"(p));
    return a;
}

__device__ __forceinline__ uint32_t pack2(float a, float b) {
    __nv_bfloat162 h = __floats2bfloat162_rn(a, b);   // a -> low half
    return *reinterpret_cast<uint32_t*>(&h);
}

__device__ __forceinline__ void ldsm_x4(uint32_t addr, uint32_t& r0, uint32_t& r1,
                                        uint32_t& r2, uint32_t& r3) {
    asm volatile("ldmatrix.sync.aligned.m8n8.x4.shared.b16 {%0,%1,%2,%3}, [%4];"
                 : "=r"(r0), "=r"(r1), "=r"(r2), "=r"(r3) : "r"(addr));
}

__device__ __forceinline__ void mma_bf16(float* c, const uint32_t* a,
                                         uint32_t b0, uint32_t b1) {
    asm volatile(
        "mma.sync.aligned.m16n8k16.row.col.f32.bf16.bf16.f32 "
        "{%0,%1,%2,%3}, {%4,%5,%6,%7}, {%8,%9}, {%0,%1,%2,%3};"
        : "+f"(c[0]), "+f"(c[1]), "+f"(c[2]), "+f"(c[3])
        : "r"(a[0]), "r"(a[1]), "r"(a[2]), "r"(a[3]), "r"(b0), "r"(b1));
}

__device__ __forceinline__ float negd(float cross, float s2) {
    float d2 = fmaxf(fmaf(-2.0f, cross, s2), 1e-12f);
    float rt;
    asm("sqrt.approx.f32 %0, %1;" : "=f"(rt) : "f"(d2));
    return -rt;
}

// Permuted SMEM row for prototype p: within each 16-proto group, proto 4t+d
// goes to row slot (d>>1)*8 + 2t + (d&1), so that lane t's accumulator quad
// over a frag pair equals protos 16nb+4t..+3.
__device__ __forceinline__ int b_perm_row(int p) {
    const int grp = p >> 4;          // 16-proto group (0..15)
    const int r   = p & 15;
    const int t_  = r >> 2;
    const int d   = r & 3;
    return grp * 16 + (d >> 1) * 8 + 2 * t_ + (d & 1);
}

__global__ void __launch_bounds__(kThreads, 1)
proto_kernel(const float* __restrict__ emb, const float* __restrict__ proto,
             float* __restrict__ out, long long nEmb, long long nTiles)
{
    extern __shared__ char smem[];
    const uint32_t sbase = smem_u32(smem);
    const int tid  = (int)threadIdx.x;
    const int lane = tid & 31;
    const int wid  = tid >> 5;
    const int warp_m = wid & 3;    // rows warp_m*32 .. +32
    const int warp_n = wid >> 2;   // cols warp_n*64 .. +64
    const int g = lane >> 2, t = lane & 3;

    float* e2s = reinterpret_cast<float*>(smem + OFF_E2);
    float* p2s = reinterpret_cast<float*>(smem + OFF_P2);

    // ------- setup: prototypes -> bf16 SMEM (permuted rows) + fp32 p2 (2 thr/row) -------
    {
        const int p = tid >> 1, half = tid & 1;
        const float4* src = reinterpret_cast<const float4*>(proto + (size_t)p * kD)
                          + half * 16;
        char* dst = smem + OFF_B + (uint32_t)b_perm_row(p) * ROWB + (uint32_t)half * 128u;
        float acc = 0.f;
#pragma unroll
        for (int j = 0; j < 4; ++j) {
            float4 v0 = __ldg(src + 4 * j + 0);
            float4 v1 = __ldg(src + 4 * j + 1);
            float4 v2 = __ldg(src + 4 * j + 2);
            float4 v3 = __ldg(src + 4 * j + 3);
            acc = fmaf(v0.x, v0.x, acc); acc = fmaf(v0.y, v0.y, acc);
            acc = fmaf(v0.z, v0.z, acc); acc = fmaf(v0.w, v0.w, acc);
            acc = fmaf(v1.x, v1.x, acc); acc = fmaf(v1.y, v1.y, acc);
            acc = fmaf(v1.z, v1.z, acc); acc = fmaf(v1.w, v1.w, acc);
            acc = fmaf(v2.x, v2.x, acc); acc = fmaf(v2.y, v2.y, acc);
            acc = fmaf(v2.z, v2.z, acc); acc = fmaf(v2.w, v2.w, acc);
            acc = fmaf(v3.x, v3.x, acc); acc = fmaf(v3.y, v3.y, acc);
            acc = fmaf(v3.z, v3.z, acc); acc = fmaf(v3.w, v3.w, acc);
            uint4 u0, u1;
            u0.x = pack2(v0.x, v0.y); u0.y = pack2(v0.z, v0.w);
            u0.z = pack2(v1.x, v1.y); u0.w = pack2(v1.z, v1.w);
            u1.x = pack2(v2.x, v2.y); u1.y = pack2(v2.z, v2.w);
            u1.z = pack2(v3.x, v3.y); u1.w = pack2(v3.z, v3.w);
            *reinterpret_cast<uint4*>(dst + 32 * j)      = u0;
            *reinterpret_cast<uint4*>(dst + 32 * j + 16) = u1;
        }
        acc += __shfl_xor_sync(0xffffffffu, acc, 1);
        if (half == 0) p2s[p] = acc;   // p2 in NATURAL order
    }

    const long long grid = (long long)gridDim.x;
    const long long t0   = (long long)blockIdx.x;
    const long long T    = (t0 < nTiles) ? ((nTiles - t0 + grid - 1) / grid) : 0;

    // A loader mapping: 4 threads per row, 32 cols (8 float4) each.
    const int lrow = tid >> 2;
    const int lq   = tid & 3;

    // ldmatrix per-lane offset
    const uint32_t lm_off = (uint32_t)((lane & 7) + ((lane >> 3) & 1) * 8) * ROWB
                          + (uint32_t)((lane >> 4) & 1) * 16u;
    const uint32_t a_base0 = sbase + OFF_A + (uint32_t)(warp_m * 32) * ROWB + lm_off;
    const uint32_t b_base  = sbase + OFF_B + (uint32_t)(warp_n * 64) * ROWB + lm_off;

    // -------- prologue: load tile 0 into buffer 0 --------
    if (T > 0) {
        long long grow = t0 * kTM + lrow;
        if (grow >= nEmb) grow = nEmb - 1;
        const float4* src = reinterpret_cast<const float4*>(emb + grow * (long long)kD)
                          + lq * 8;
        char* dst = smem + OFF_A + (uint32_t)lrow * ROWB + (uint32_t)lq * 64u;
        float e2 = 0.f;
#pragma unroll
        for (int j = 0; j < 2; ++j) {
            float4 v0 = __ldcs(src + 4 * j + 0);
            float4 v1 = __ldcs(src + 4 * j + 1);
            float4 v2 = __ldcs(src + 4 * j + 2);
            float4 v3 = __ldcs(src + 4 * j + 3);
            e2 = fmaf(v0.x, v0.x, e2); e2 = fmaf(v0.y, v0.y, e2);
            e2 = fmaf(v0.z, v0.z, e2); e2 = fmaf(v0.w, v0.w, e2);
            e2 = fmaf(v1.x, v1.x, e2); e2 = fmaf(v1.y, v1.y, e2);
            e2 = fmaf(v1.z, v1.z, e2); e2 = fmaf(v1.w, v1.w, e2);
            e2 = fmaf(v2.x, v2.x, e2); e2 = fmaf(v2.y, v2.y, e2);
            e2 = fmaf(v2.z, v2.z, e2); e2 = fmaf(v2.w, v2.w, e2);
            e2 = fmaf(v3.x, v3.x, e2); e2 = fmaf(v3.y, v3.y, e2);
            e2 = fmaf(v3.z, v3.z, e2); e2 = fmaf(v3.w, v3.w, e2);
            uint4 u0, u1;
            u0.x = pack2(v0.x, v0.y); u0.y = pack2(v0.z, v0.w);
            u0.z = pack2(v1.x, v1.y); u0.w = pack2(v1.z, v1.w);
            u1.x = pack2(v2.x, v2.y); u1.y = pack2(v2.z, v2.w);
            u1.z = pack2(v3.x, v3.y); u1.w = pack2(v3.z, v3.w);
            *reinterpret_cast<uint4*>(dst + 32 * j)      = u0;
            *reinterpret_cast<uint4*>(dst + 32 * j + 16) = u1;
        }
        e2 += __shfl_xor_sync(0xffffffffu, e2, 1);
        e2 += __shfl_xor_sync(0xffffffffu, e2, 2);
        if (lq == 0) e2s[lrow] = e2;
    }
    __syncthreads();

    // ---------------- main loop ----------------
    for (long long ii = 0; ii < T; ++ii) {
        const int s = (int)(ii & 1);
        const long long tile = t0 + ii * grid;

        // ---- issue next tile's global loads early (regs) ----
        float4 v[8];
        const bool more = (ii + 1 < T);
        if (more) {
            long long grow = (tile + grid) * kTM + lrow;
            if (grow >= nEmb) grow = nEmb - 1;
            const float4* src = reinterpret_cast<const float4*>(emb + grow * (long long)kD)
                              + lq * 8;
#pragma unroll
            for (int i = 0; i < 8; ++i) v[i] = __ldcs(src + i);
        }

        // ---- GEMM: 32x64 per warp from smem buffer s ----
        float acc[2][8][4];
#pragma unroll
        for (int mb = 0; mb < 2; ++mb)
#pragma unroll
            for (int nf = 0; nf < 8; ++nf)
#pragma unroll
                for (int q = 0; q < 4; ++q) acc[mb][nf][q] = 0.f;

        const uint32_t a_base = a_base0 + (uint32_t)s * A_BUF;
#pragma unroll
        for (int kb = 0; kb < 8; ++kb) {
            const uint32_t kboff = (uint32_t)(kb * 32);
            uint32_t a[2][4];
            ldsm_x4(a_base + kboff,              a[0][0], a[0][1], a[0][2], a[0][3]);
            ldsm_x4(a_base + 16u * ROWB + kboff, a[1][0], a[1][1], a[1][2], a[1][3]);
#pragma unroll
            for (int nb = 0; nb < 4; ++nb) {
                uint32_t b0, b1, b2, b3;
                ldsm_x4(b_base + (uint32_t)(nb * 16) * ROWB + kboff, b0, b1, b2, b3);
                mma_bf16(acc[0][2 * nb],     a[0], b0, b2);
                mma_bf16(acc[0][2 * nb + 1], a[0], b1, b3);
                mma_bf16(acc[1][2 * nb],     a[1], b0, b2);
                mma_bf16(acc[1][2 * nb + 1], a[1], b1, b3);
            }
        }

        // ---- convert + store next tile into buffer s^1, e2 reduce ----
        if (more) {
            float e2 = 0.f;
#pragma unroll
            for (int i = 0; i < 8; ++i) {
                e2 = fmaf(v[i].x, v[i].x, e2); e2 = fmaf(v[i].y, v[i].y, e2);
                e2 = fmaf(v[i].z, v[i].z, e2); e2 = fmaf(v[i].w, v[i].w, e2);
            }
            char* dst = smem + OFF_A + (uint32_t)(s ^ 1) * A_BUF
                      + (uint32_t)lrow * ROWB + (uint32_t)lq * 64u;
#pragma unroll
            for (int j = 0; j < 2; ++j) {
                uint4 u0, u1;
                u0.x = pack2(v[4 * j + 0].x, v[4 * j + 0].y);
                u0.y = pack2(v[4 * j + 0].z, v[4 * j + 0].w);
                u0.z = pack2(v[4 * j + 1].x, v[4 * j + 1].y);
                u0.w = pack2(v[4 * j + 1].z, v[4 * j + 1].w);
                u1.x = pack2(v[4 * j + 2].x, v[4 * j + 2].y);
                u1.y = pack2(v[4 * j + 2].z, v[4 * j + 2].w);
                u1.z = pack2(v[4 * j + 3].x, v[4 * j + 3].y);
                u1.w = pack2(v[4 * j + 3].z, v[4 * j + 3].w);
                *reinterpret_cast<uint4*>(dst + 32 * j)      = u0;
                *reinterpret_cast<uint4*>(dst + 32 * j + 16) = u1;
            }
            e2 += __shfl_xor_sync(0xffffffffu, e2, 1);
            e2 += __shfl_xor_sync(0xffffffffu, e2, 2);
            if (lq == 0) e2s[(s ^ 1) * 128 + lrow] = e2;
        }

        // ---- pre-read e2 for this tile's epilogue (iter i+1 overwrites e2s[s]) ----
        float e2r[2][2];
        {
            const float* e2c = e2s + s * 128;
#pragma unroll
            for (int mb = 0; mb < 2; ++mb)
#pragma unroll
                for (int h = 0; h < 2; ++h)
                    e2r[mb][h] = e2c[warp_m * 32 + mb * 16 + h * 8 + g];
        }

        // Barrier guards only the A-buffer handoff; epilogue runs after it and
        // overlaps the next iteration's GEMM on other warps.
        __syncthreads();

        // ---- fused distance epilogue: permuted layout -> float4 STG ----
#pragma unroll
        for (int mb = 0; mb < 2; ++mb) {
#pragma unroll
            for (int h = 0; h < 2; ++h) {
                const int row = warp_m * 32 + mb * 16 + h * 8 + g;
                const long long r = tile * kTM + row;
                if (r < nEmb) {
                    const float e2m = e2r[mb][h];
                    float* orow = out + (size_t)r * kP;
#pragma unroll
                    for (int nb = 0; nb < 4; ++nb) {
                        const int col = warp_n * 64 + nb * 16 + 4 * t;
                        const float4 pv = *reinterpret_cast<const float4*>(p2s + col);
                        float4 o;
                        o.x = negd(acc[mb][2 * nb][h * 2 + 0],     e2m + pv.x);
                        o.y = negd(acc[mb][2 * nb][h * 2 + 1],     e2m + pv.y);
                        o.z = negd(acc[mb][2 * nb + 1][h * 2 + 0], e2m + pv.z);
                        o.w = negd(acc[mb][2 * nb + 1][h * 2 + 1], e2m + pv.w);
                        __stcs(reinterpret_cast<float4*>(orow + col), o);
                    }
                }
            }
        }
    }
}

extern "C" void kernel_launch(void* const* d_in, const int* in_sizes, int n_in,
                              void* d_out, int out_size)
{
    const float* emb   = (const float*)d_in[0];
    const float* proto = (const float*)d_in[1];
    float* out = (float*)d_out;

    const long long nEmb   = (long long)in_sizes[0] / kD;
    const long long nTiles = (nEmb + kTM - 1) / kTM;

    cudaFuncSetAttribute(proto_kernel, cudaFuncAttributeMaxDynamicSharedMemorySize,
                         (int)SMEM_TOTAL);
    int dev = 0;
    cudaGetDevice(&dev);
    int nsm = 148;
    cudaDeviceGetAttribute(&nsm, cudaDevAttrMultiProcessorCount, dev);
    const int gridx = (int)((nTiles < (long long)nsm) ? nTiles : (long long)nsm);

    proto_kernel<<<gridx, kThreads, SMEM_TOTAL>>>(emb, proto, out, nEmb, nTiles);
}

// round 10
// speedup vs baseline: 1.1088x; 1.1088x over previous
#include <cuda_runtime.h>
#include <cuda_bf16.h>
#include <cstdint>

// out[n,0,p] = -sqrt(max(||e_n||^2 + ||p_p||^2 - 2 e_n.p_p, 1e-12))
// N=500000, P=256, D=128.  sm_103 HMMA (bf16 mma.sync).
// Warp-specialized: 4 producer warps stream A tiles (fp32->bf16 + exact fp32 e2)
// through a 6-stage SMEM ring; 8 consumer warps run GEMM + fused sqrt epilogue
// (permuted-B float4 STG). Named-barrier full/empty pairs per stage.

static constexpr int kD = 128;
static constexpr int kP = 256;
static constexpr int kTM = 64;            // rows per tile
static constexpr int kThreads = 384;      // 8 consumer + 4 producer warps
static constexpr int kStages = 6;

static constexpr uint32_t ROWB = 272;     // bf16 row: 256B + 16B pad (conflict-free ldsm)
static constexpr uint32_t A_BUF = 64u * ROWB;                 // 17408
static constexpr uint32_t OFF_P2 = 0;                         // 256 f32
static constexpr uint32_t OFF_E2 = 1024;                      // 6 x 64 f32
static constexpr uint32_t OFF_A  = 4096;                      // 6 x A_BUF
static constexpr uint32_t OFF_B  = OFF_A + kStages * A_BUF;   // 108544
static constexpr uint32_t SMEM_TOTAL = OFF_B + 256u * ROWB;   // 178176

__device__ __forceinline__ uint32_t smem_u32(const void* p) {
    uint32_t a;
    asm("{ .reg .u64 t; cvta.to.shared.u64 t, %1; cvt.u32.u64 %0, t; }" : "=r"(a) : "l"(p));
    return a;
}

__device__ __forceinline__ uint32_t pack2(float a, float b) {
    __nv_bfloat162 h = __floats2bfloat162_rn(a, b);   // a -> low half
    return *reinterpret_cast<uint32_t*>(&h);
}

__device__ __forceinline__ void bar_syncn(int id) {
    asm volatile("bar.sync %0, 384;" :: "r"(id) : "memory");
}
__device__ __forceinline__ void bar_arriven(int id) {
    asm volatile("bar.arrive %0, 384;" :: "r"(id) : "memory");
}

__device__ __forceinline__ void ldsm_x4(uint32_t addr, uint32_t& r0, uint32_t& r1,
                                        uint32_t& r2, uint32_t& r3) {
    asm volatile("ldmatrix.sync.aligned.m8n8.x4.shared.b16 {%0,%1,%2,%3}, [%4];"
                 : "=r"(r0), "=r"(r1), "=r"(r2), "=r"(r3) : "r"(addr));
}

__device__ __forceinline__ void mma_bf16(float* c, const uint32_t* a,
                                         uint32_t b0, uint32_t b1) {
    asm volatile(
        "mma.sync.aligned.m16n8k16.row.col.f32.bf16.bf16.f32 "
        "{%0,%1,%2,%3}, {%4,%5,%6,%7}, {%8,%9}, {%0,%1,%2,%3};"
        : "+f"(c[0]), "+f"(c[1]), "+f"(c[2]), "+f"(c[3])
        : "r"(a[0]), "r"(a[1]), "r"(a[2]), "r"(a[3]), "r"(b0), "r"(b1));
}

__device__ __forceinline__ float negd(float cross, float s2) {
    float d2 = fmaxf(fmaf(-2.0f, cross, s2), 1e-12f);
    float rt;
    asm("sqrt.approx.f32 %0, %1;" : "=f"(rt) : "f"(d2));
    return -rt;
}

// Permuted SMEM row for prototype p (R8 scheme): lane t's accumulator quad over
// a frag pair = 4 consecutive prototypes -> float4 epilogue stores.
__device__ __forceinline__ int b_perm_row(int p) {
    const int grp = p >> 4;
    const int r   = p & 15;
    const int t_  = r >> 2;
    const int d   = r & 3;
    return grp * 16 + (d >> 1) * 8 + 2 * t_ + (d & 1);
}

__global__ void __launch_bounds__(kThreads, 1)
proto_kernel(const float* __restrict__ emb, const float* __restrict__ proto,
             float* __restrict__ out, long long nEmb, long long nTiles)
{
    extern __shared__ char smem[];
    const uint32_t sbase = smem_u32(smem);
    const int tid  = (int)threadIdx.x;
    const int lane = tid & 31;
    const int wid  = tid >> 5;

    float* e2s = reinterpret_cast<float*>(smem + OFF_E2);
    float* p2s = reinterpret_cast<float*>(smem + OFF_P2);

    // ------- setup: prototypes -> bf16 SMEM (permuted rows) + fp32 p2 (1 thr/row) -------
    if (tid < 256) {
        const int p = tid;
        const float4* src = reinterpret_cast<const float4*>(proto + (size_t)p * kD);
        char* dst = smem + OFF_B + (uint32_t)b_perm_row(p) * ROWB;
        float acc = 0.f;
#pragma unroll
        for (int j = 0; j < 8; ++j) {
            float4 v0 = __ldg(src + 4 * j + 0);
            float4 v1 = __ldg(src + 4 * j + 1);
            float4 v2 = __ldg(src + 4 * j + 2);
            float4 v3 = __ldg(src + 4 * j + 3);
            acc = fmaf(v0.x, v0.x, acc); acc = fmaf(v0.y, v0.y, acc);
            acc = fmaf(v0.z, v0.z, acc); acc = fmaf(v0.w, v0.w, acc);
            acc = fmaf(v1.x, v1.x, acc); acc = fmaf(v1.y, v1.y, acc);
            acc = fmaf(v1.z, v1.z, acc); acc = fmaf(v1.w, v1.w, acc);
            acc = fmaf(v2.x, v2.x, acc); acc = fmaf(v2.y, v2.y, acc);
            acc = fmaf(v2.z, v2.z, acc); acc = fmaf(v2.w, v2.w, acc);
            acc = fmaf(v3.x, v3.x, acc); acc = fmaf(v3.y, v3.y, acc);
            acc = fmaf(v3.z, v3.z, acc); acc = fmaf(v3.w, v3.w, acc);
            uint4 u0, u1;
            u0.x = pack2(v0.x, v0.y); u0.y = pack2(v0.z, v0.w);
            u0.z = pack2(v1.x, v1.y); u0.w = pack2(v1.z, v1.w);
            u1.x = pack2(v2.x, v2.y); u1.y = pack2(v2.z, v2.w);
            u1.z = pack2(v3.x, v3.y); u1.w = pack2(v3.z, v3.w);
            *reinterpret_cast<uint4*>(dst + 32 * j)      = u0;
            *reinterpret_cast<uint4*>(dst + 32 * j + 16) = u1;
        }
        p2s[p] = acc;
    }
    __syncthreads();

    const long long grid = (long long)gridDim.x;
    const long long t0   = (long long)blockIdx.x;
    const long long T    = (t0 < nTiles) ? ((nTiles - t0 + grid - 1) / grid) : 0;

    if (wid < 8) {
        // ============================ CONSUMERS ============================
        const int warp_m = wid & 1;    // rows warp_m*32 .. +32
        const int warp_n = wid >> 1;   // cols warp_n*64 .. +64
        const int g = lane >> 2, t = lane & 3;

        const uint32_t lm_off = (uint32_t)((lane & 7) + ((lane >> 3) & 1) * 8) * ROWB
                              + (uint32_t)((lane >> 4) & 1) * 16u;
        const uint32_t a_base0 = sbase + OFF_A + (uint32_t)(warp_m * 32) * ROWB + lm_off;
        const uint32_t b_base  = sbase + OFF_B + (uint32_t)(warp_n * 64) * ROWB + lm_off;

        // Seed all empty barriers (consumers' phase-0 arrivals).
#pragma unroll
        for (int s = 0; s < kStages; ++s) bar_arriven(7 + s);

        for (long long ii = 0; ii < T; ++ii) {
            const int s = (int)(ii % kStages);
            const long long tile = t0 + ii * grid;

            bar_syncn(1 + s);   // wait: stage s full

            // e2 for this warp's rows
            float e2r[2][2];
            {
                const float* e2c = e2s + s * 64;
#pragma unroll
                for (int mb = 0; mb < 2; ++mb)
#pragma unroll
                    for (int h = 0; h < 2; ++h)
                        e2r[mb][h] = e2c[warp_m * 32 + mb * 16 + h * 8 + g];
            }

            // ---- GEMM: 32x64 per warp from stage s ----
            float acc[2][8][4];
#pragma unroll
            for (int mb = 0; mb < 2; ++mb)
#pragma unroll
                for (int nf = 0; nf < 8; ++nf)
#pragma unroll
                    for (int q = 0; q < 4; ++q) acc[mb][nf][q] = 0.f;

            const uint32_t a_base = a_base0 + (uint32_t)s * A_BUF;
#pragma unroll
            for (int kb = 0; kb < 8; ++kb) {
                const uint32_t kboff = (uint32_t)(kb * 32);
                uint32_t a[2][4];
                ldsm_x4(a_base + kboff,              a[0][0], a[0][1], a[0][2], a[0][3]);
                ldsm_x4(a_base + 16u * ROWB + kboff, a[1][0], a[1][1], a[1][2], a[1][3]);
#pragma unroll
                for (int nb = 0; nb < 4; ++nb) {
                    uint32_t b0, b1, b2, b3;
                    ldsm_x4(b_base + (uint32_t)(nb * 16) * ROWB + kboff, b0, b1, b2, b3);
                    mma_bf16(acc[0][2 * nb],     a[0], b0, b2);
                    mma_bf16(acc[0][2 * nb + 1], a[0], b1, b3);
                    mma_bf16(acc[1][2 * nb],     a[1], b0, b2);
                    mma_bf16(acc[1][2 * nb + 1], a[1], b1, b3);
                }
            }

            // ---- fused distance epilogue (permuted layout -> float4 STG) ----
#pragma unroll
            for (int mb = 0; mb < 2; ++mb) {
#pragma unroll
                for (int h = 0; h < 2; ++h) {
                    const int row = warp_m * 32 + mb * 16 + h * 8 + g;
                    const long long r = tile * kTM + row;
                    if (r < nEmb) {
                        const float e2m = e2r[mb][h];
                        float* orow = out + (size_t)r * kP;
#pragma unroll
                        for (int nb = 0; nb < 4; ++nb) {
                            const int col = warp_n * 64 + nb * 16 + 4 * t;
                            const float4 pv = *reinterpret_cast<const float4*>(p2s + col);
                            float4 o;
                            o.x = negd(acc[mb][2 * nb][h * 2 + 0],     e2m + pv.x);
                            o.y = negd(acc[mb][2 * nb][h * 2 + 1],     e2m + pv.y);
                            o.z = negd(acc[mb][2 * nb + 1][h * 2 + 0], e2m + pv.z);
                            o.w = negd(acc[mb][2 * nb + 1][h * 2 + 1], e2m + pv.w);
                            __stcs(reinterpret_cast<float4*>(orow + col), o);
                        }
                    }
                }
            }

            bar_arriven(7 + s);   // stage s consumed
        }
    } else {
        // ============================ PRODUCERS ============================
        const int ptid = tid - 256;        // 0..127
        const int prow = ptid >> 2;        // 0..31 (row within 32-row pass)
        const int plq  = ptid & 3;         // 32-col chunk

        for (long long ii = 0; ii < T; ++ii) {
            const int s = (int)(ii % kStages);
            const long long tile = t0 + ii * grid;

            // LDG both passes into regs (before the empty-wait: overlaps latency)
            float4 v[16];
            float e2p[2];
#pragma unroll
            for (int pass = 0; pass < 2; ++pass) {
                long long grow = tile * kTM + prow + 32 * pass;
                if (grow >= nEmb) grow = nEmb - 1;
                const float4* src = reinterpret_cast<const float4*>(emb + grow * (long long)kD)
                                  + plq * 8;
                float e2 = 0.f;
#pragma unroll
                for (int i = 0; i < 8; ++i) {
                    float4 x = __ldcs(src + i);
                    v[pass * 8 + i] = x;
                    e2 = fmaf(x.x, x.x, e2); e2 = fmaf(x.y, x.y, e2);
                    e2 = fmaf(x.z, x.z, e2); e2 = fmaf(x.w, x.w, e2);
                }
                e2p[pass] = e2;
            }

            bar_syncn(7 + s);   // wait: stage s empty

#pragma unroll
            for (int pass = 0; pass < 2; ++pass) {
                const int row = prow + 32 * pass;
                char* dst = smem + OFF_A + (uint32_t)s * A_BUF
                          + (uint32_t)row * ROWB + (uint32_t)plq * 64u;
                const float4* vv = &v[pass * 8];
#pragma unroll
                for (int j = 0; j < 2; ++j) {
                    uint4 u0, u1;
                    u0.x = pack2(vv[4 * j + 0].x, vv[4 * j + 0].y);
                    u0.y = pack2(vv[4 * j + 0].z, vv[4 * j + 0].w);
                    u0.z = pack2(vv[4 * j + 1].x, vv[4 * j + 1].y);
                    u0.w = pack2(vv[4 * j + 1].z, vv[4 * j + 1].w);
                    u1.x = pack2(vv[4 * j + 2].x, vv[4 * j + 2].y);
                    u1.y = pack2(vv[4 * j + 2].z, vv[4 * j + 2].w);
                    u1.z = pack2(vv[4 * j + 3].x, vv[4 * j + 3].y);
                    u1.w = pack2(vv[4 * j + 3].z, vv[4 * j + 3].w);
                    *reinterpret_cast<uint4*>(dst + 32 * j)      = u0;
                    *reinterpret_cast<uint4*>(dst + 32 * j + 16) = u1;
                }
                float e2 = e2p[pass];
                e2 += __shfl_xor_sync(0xffffffffu, e2, 1);
                e2 += __shfl_xor_sync(0xffffffffu, e2, 2);
                if (plq == 0) e2s[s * 64 + row] = e2;
            }

            bar_arriven(1 + s);   // stage s full
        }
    }
}

extern "C" void kernel_launch(void* const* d_in, const int* in_sizes, int n_in,
                              void* d_out, int out_size)
{
    const float* emb   = (const float*)d_in[0];
    const float* proto = (const float*)d_in[1];
    float* out = (float*)d_out;

    const long long nEmb   = (long long)in_sizes[0] / kD;
    const long long nTiles = (nEmb + kTM - 1) / kTM;

    cudaFuncSetAttribute(proto_kernel, cudaFuncAttributeMaxDynamicSharedMemorySize,
                         (int)SMEM_TOTAL);
    int dev = 0;
    cudaGetDevice(&dev);
    int nsm = 148;
    cudaDeviceGetAttribute(&nsm, cudaDevAttrMultiProcessorCount, dev);
    const int gridx = (int)((nTiles < (long long)nsm) ? nTiles : (long long)nsm);

    proto_kernel<<<gridx, kThreads, SMEM_TOTAL>>>(emb, proto, out, nEmb, nTiles);
}

// round 11
// speedup vs baseline: 1.1581x; 1.0444x over previous
#include <cuda_runtime.h>
#include <cuda_fp16.h>
#include <cstdint>

// out[n,0,p] = -sqrt(max(||e_n||^2 + ||p_p||^2 - 2 e_n.p_p, 1e-12))
// N=500000, P=256, D=128.  sm_103 HMMA (fp16 mma.sync, f16 accumulators).
// Warp-specialized: 4 producer warps stream A tiles (fp32->fp16 + exact fp32 e2)
// through a 6-stage SMEM ring; 8 consumer warps process TILE PAIRS so each
// B fragment load is shared across two tiles (halves B-ldsm traffic).
// Fused fp32 sqrt epilogue with permuted-B float4 STG.

static constexpr int kD = 128;
static constexpr int kP = 256;
static constexpr int kTM = 64;            // rows per tile
static constexpr int kThreads = 384;      // 8 consumer + 4 producer warps
static constexpr int kStages = 6;

static constexpr uint32_t ROWB = 272;     // fp16 row: 256B + 16B pad (conflict-free ldsm)
static constexpr uint32_t A_BUF = 64u * ROWB;                 // 17408
static constexpr uint32_t OFF_P2 = 0;                         // 256 f32
static constexpr uint32_t OFF_E2 = 1024;                      // 6 x 64 f32
static constexpr uint32_t OFF_A  = 4096;                      // 6 x A_BUF
static constexpr uint32_t OFF_B  = OFF_A + kStages * A_BUF;   // 108544
static constexpr uint32_t SMEM_TOTAL = OFF_B + 256u * ROWB;   // 178176

__device__ __forceinline__ uint32_t smem_u32(const void* p) {
    uint32_t a;
    asm("{ .reg .u64 t; cvta.to.shared.u64 t, %1; cvt.u32.u64 %0, t; }" : "=r"(a) : "l"(p));
    return a;
}

__device__ __forceinline__ uint32_t pack2h(float a, float b) {
    __half2 h = __floats2half2_rn(a, b);   // a -> low half
    return *reinterpret_cast<uint32_t*>(&h);
}

__device__ __forceinline__ void bar_syncn(int id) {
    asm volatile("bar.sync %0, 384;" :: "r"(id) : "memory");
}
__device__ __forceinline__ void bar_arriven(int id) {
    asm volatile("bar.arrive %0, 384;" :: "r"(id) : "memory");
}

__device__ __forceinline__ void ldsm_x4(uint32_t addr, uint32_t& r0, uint32_t& r1,
                                        uint32_t& r2, uint32_t& r3) {
    asm volatile("ldmatrix.sync.aligned.m8n8.x4.shared.b16 {%0,%1,%2,%3}, [%4];"
                 : "=r"(r0), "=r"(r1), "=r"(r2), "=r"(r3) : "r"(addr));
}

// f16 x f16 -> f16 accumulate (2 acc regs, each f16x2: rows g/g+8, cols 2t,2t+1)
__device__ __forceinline__ void mma_f16(uint32_t* c, const uint32_t* a,
                                        uint32_t b0, uint32_t b1) {
    asm volatile(
        "mma.sync.aligned.m16n8k16.row.col.f16.f16.f16.f16 "
        "{%0,%1}, {%2,%3,%4,%5}, {%6,%7}, {%0,%1};"
        : "+r"(c[0]), "+r"(c[1])
        : "r"(a[0]), "r"(a[1]), "r"(a[2]), "r"(a[3]), "r"(b0), "r"(b1));
}

__device__ __forceinline__ float negd(float cross, float s2) {
    float d2 = fmaxf(fmaf(-2.0f, cross, s2), 1e-12f);
    float rt;
    asm("sqrt.approx.f32 %0, %1;" : "=f"(rt) : "f"(d2));
    return -rt;
}

// Permuted SMEM row for prototype p: lane t's accumulator quad over a frag
// pair = 4 consecutive prototypes -> float4 epilogue stores.
__device__ __forceinline__ int b_perm_row(int p) {
    const int grp = p >> 4;
    const int r   = p & 15;
    const int t_  = r >> 2;
    const int d   = r & 3;
    return grp * 16 + (d >> 1) * 8 + 2 * t_ + (d & 1);
}

__global__ void __launch_bounds__(kThreads, 1)
proto_kernel(const float* __restrict__ emb, const float* __restrict__ proto,
             float* __restrict__ out, long long nEmb, long long nTiles)
{
    extern __shared__ char smem[];
    const uint32_t sbase = smem_u32(smem);
    const int tid  = (int)threadIdx.x;
    const int lane = tid & 31;
    const int wid  = tid >> 5;

    float* e2s = reinterpret_cast<float*>(smem + OFF_E2);
    float* p2s = reinterpret_cast<float*>(smem + OFF_P2);

    // ------- setup: prototypes -> fp16 SMEM (permuted rows) + fp32 p2 -------
    if (tid < 256) {
        const int p = tid;
        const float4* src = reinterpret_cast<const float4*>(proto + (size_t)p * kD);
        char* dst = smem + OFF_B + (uint32_t)b_perm_row(p) * ROWB;
        float acc = 0.f;
#pragma unroll
        for (int j = 0; j < 8; ++j) {
            float4 v0 = __ldg(src + 4 * j + 0);
            float4 v1 = __ldg(src + 4 * j + 1);
            float4 v2 = __ldg(src + 4 * j + 2);
            float4 v3 = __ldg(src + 4 * j + 3);
            acc = fmaf(v0.x, v0.x, acc); acc = fmaf(v0.y, v0.y, acc);
            acc = fmaf(v0.z, v0.z, acc); acc = fmaf(v0.w, v0.w, acc);
            acc = fmaf(v1.x, v1.x, acc); acc = fmaf(v1.y, v1.y, acc);
            acc = fmaf(v1.z, v1.z, acc); acc = fmaf(v1.w, v1.w, acc);
            acc = fmaf(v2.x, v2.x, acc); acc = fmaf(v2.y, v2.y, acc);
            acc = fmaf(v2.z, v2.z, acc); acc = fmaf(v2.w, v2.w, acc);
            acc = fmaf(v3.x, v3.x, acc); acc = fmaf(v3.y, v3.y, acc);
            acc = fmaf(v3.z, v3.z, acc); acc = fmaf(v3.w, v3.w, acc);
            uint4 u0, u1;
            u0.x = pack2h(v0.x, v0.y); u0.y = pack2h(v0.z, v0.w);
            u0.z = pack2h(v1.x, v1.y); u0.w = pack2h(v1.z, v1.w);
            u1.x = pack2h(v2.x, v2.y); u1.y = pack2h(v2.z, v2.w);
            u1.z = pack2h(v3.x, v3.y); u1.w = pack2h(v3.z, v3.w);
            *reinterpret_cast<uint4*>(dst + 32 * j)      = u0;
            *reinterpret_cast<uint4*>(dst + 32 * j + 16) = u1;
        }
        p2s[p] = acc;
    }
    __syncthreads();

    const long long grid = (long long)gridDim.x;
    const long long t0   = (long long)blockIdx.x;
    const long long T    = (t0 < nTiles) ? ((nTiles - t0 + grid - 1) / grid) : 0;

    if (wid < 8) {
        // ============================ CONSUMERS ============================
        const int warp_m = wid & 1;    // rows warp_m*32 .. +32
        const int warp_n = wid >> 1;   // cols warp_n*64 .. +64
        const int g = lane >> 2, t = lane & 3;

        const uint32_t lm_off = (uint32_t)((lane & 7) + ((lane >> 3) & 1) * 8) * ROWB
                              + (uint32_t)((lane >> 4) & 1) * 16u;
        const uint32_t a_base0 = sbase + OFF_A + (uint32_t)(warp_m * 32) * ROWB + lm_off;
        const uint32_t b_base  = sbase + OFF_B + (uint32_t)(warp_n * 64) * ROWB + lm_off;

        // Seed all empty barriers (consumers' phase-0 arrivals).
#pragma unroll
        for (int s = 0; s < kStages; ++s) bar_arriven(7 + s);

        for (long long ii = 0; ii < T; ii += 2) {
            const bool pair = (ii + 1 < T);
            const int s0 = (int)(ii % kStages);
            const int s1 = (int)((ii + 1) % kStages);
            const long long tile0 = t0 + ii * grid;
            const long long tile1 = tile0 + grid;

            bar_syncn(1 + s0);              // stage s0 full
            if (pair) bar_syncn(1 + s1);    // stage s1 full

            // e2 for this warp's rows, both tiles
            float e2r[2][2][2];             // [tile][mb][h]
#pragma unroll
            for (int mb = 0; mb < 2; ++mb)
#pragma unroll
                for (int h = 0; h < 2; ++h) {
                    const int row = warp_m * 32 + mb * 16 + h * 8 + g;
                    e2r[0][mb][h] = e2s[s0 * 64 + row];
                    e2r[1][mb][h] = pair ? e2s[s1 * 64 + row] : 0.f;
                }

            // ---- GEMM: two 32x64 tiles sharing B fragments ----
            uint32_t acc0[2][8][2], acc1[2][8][2];
#pragma unroll
            for (int mb = 0; mb < 2; ++mb)
#pragma unroll
                for (int nf = 0; nf < 8; ++nf)
#pragma unroll
                    for (int q = 0; q < 2; ++q) { acc0[mb][nf][q] = 0u; acc1[mb][nf][q] = 0u; }

            const uint32_t ab0 = a_base0 + (uint32_t)s0 * A_BUF;
            const uint32_t ab1 = a_base0 + (uint32_t)s1 * A_BUF;
#pragma unroll
            for (int kb = 0; kb < 8; ++kb) {
                const uint32_t kboff = (uint32_t)(kb * 32);
                uint32_t a0[2][4], a1[2][4];
                ldsm_x4(ab0 + kboff,              a0[0][0], a0[0][1], a0[0][2], a0[0][3]);
                ldsm_x4(ab0 + 16u * ROWB + kboff, a0[1][0], a0[1][1], a0[1][2], a0[1][3]);
                if (pair) {
                    ldsm_x4(ab1 + kboff,              a1[0][0], a1[0][1], a1[0][2], a1[0][3]);
                    ldsm_x4(ab1 + 16u * ROWB + kboff, a1[1][0], a1[1][1], a1[1][2], a1[1][3]);
                }
#pragma unroll
                for (int nb = 0; nb < 4; ++nb) {
                    uint32_t b0, b1, b2, b3;
                    ldsm_x4(b_base + (uint32_t)(nb * 16) * ROWB + kboff, b0, b1, b2, b3);
                    mma_f16(acc0[0][2 * nb],     a0[0], b0, b2);
                    mma_f16(acc0[0][2 * nb + 1], a0[0], b1, b3);
                    mma_f16(acc0[1][2 * nb],     a0[1], b0, b2);
                    mma_f16(acc0[1][2 * nb + 1], a0[1], b1, b3);
                    if (pair) {
                        mma_f16(acc1[0][2 * nb],     a1[0], b0, b2);
                        mma_f16(acc1[0][2 * nb + 1], a1[0], b1, b3);
                        mma_f16(acc1[1][2 * nb],     a1[1], b0, b2);
                        mma_f16(acc1[1][2 * nb + 1], a1[1], b1, b3);
                    }
                }
            }

            // ---- epilogues (permuted layout -> float4 STG) ----
#pragma unroll
            for (int tt = 0; tt < 2; ++tt) {
                if (tt == 1 && !pair) break;
                const long long tile = tt ? tile1 : tile0;
                uint32_t (*acc)[8][2] = tt ? acc1 : acc0;
#pragma unroll
                for (int mb = 0; mb < 2; ++mb) {
#pragma unroll
                    for (int h = 0; h < 2; ++h) {
                        const int row = warp_m * 32 + mb * 16 + h * 8 + g;
                        const long long r = tile * kTM + row;
                        if (r < nEmb) {
                            const float e2m = e2r[tt][mb][h];
                            float* orow = out + (size_t)r * kP;
#pragma unroll
                            for (int nb = 0; nb < 4; ++nb) {
                                const int col = warp_n * 64 + nb * 16 + 4 * t;
                                const float4 pv = *reinterpret_cast<const float4*>(p2s + col);
                                const float2 lo = __half22float2(
                                    *reinterpret_cast<__half2*>(&acc[mb][2 * nb][h]));
                                const float2 hi = __half22float2(
                                    *reinterpret_cast<__half2*>(&acc[mb][2 * nb + 1][h]));
                                float4 o;
                                o.x = negd(lo.x, e2m + pv.x);
                                o.y = negd(lo.y, e2m + pv.y);
                                o.z = negd(hi.x, e2m + pv.z);
                                o.w = negd(hi.y, e2m + pv.w);
                                __stcs(reinterpret_cast<float4*>(orow + col), o);
                            }
                        }
                    }
                }
                bar_arriven(7 + (tt ? s1 : s0));   // stage consumed
            }
        }
    } else {
        // ============================ PRODUCERS ============================
        const int ptid = tid - 256;        // 0..127
        const int prow = ptid >> 2;        // 0..31 (row within 32-row pass)
        const int plq  = ptid & 3;         // 32-col chunk

        for (long long ii = 0; ii < T; ++ii) {
            const int s = (int)(ii % kStages);
            const long long tile = t0 + ii * grid;

            // LDG both passes into regs (before the empty-wait: overlaps latency)
            float4 v[16];
            float e2p[2];
#pragma unroll
            for (int pass = 0; pass < 2; ++pass) {
                long long grow = tile * kTM + prow + 32 * pass;
                if (grow >= nEmb) grow = nEmb - 1;
                const float4* src = reinterpret_cast<const float4*>(emb + grow * (long long)kD)
                                  + plq * 8;
                float e2 = 0.f;
#pragma unroll
                for (int i = 0; i < 8; ++i) {
                    float4 x = __ldcs(src + i);
                    v[pass * 8 + i] = x;
                    e2 = fmaf(x.x, x.x, e2); e2 = fmaf(x.y, x.y, e2);
                    e2 = fmaf(x.z, x.z, e2); e2 = fmaf(x.w, x.w, e2);
                }
                e2p[pass] = e2;
            }

            bar_syncn(7 + s);   // wait: stage s empty

#pragma unroll
            for (int pass = 0; pass < 2; ++pass) {
                const int row = prow + 32 * pass;
                char* dst = smem + OFF_A + (uint32_t)s * A_BUF
                          + (uint32_t)row * ROWB + (uint32_t)plq * 64u;
                const float4* vv = &v[pass * 8];
#pragma unroll
                for (int j = 0; j < 2; ++j) {
                    uint4 u0, u1;
                    u0.x = pack2h(vv[4 * j + 0].x, vv[4 * j + 0].y);
                    u0.y = pack2h(vv[4 * j + 0].z, vv[4 * j + 0].w);
                    u0.z = pack2h(vv[4 * j + 1].x, vv[4 * j + 1].y);
                    u0.w = pack2h(vv[4 * j + 1].z, vv[4 * j + 1].w);
                    u1.x = pack2h(vv[4 * j + 2].x, vv[4 * j + 2].y);
                    u1.y = pack2h(vv[4 * j + 2].z, vv[4 * j + 2].w);
                    u1.z = pack2h(vv[4 * j + 3].x, vv[4 * j + 3].y);
                    u1.w = pack2h(vv[4 * j + 3].z, vv[4 * j + 3].w);
                    *reinterpret_cast<uint4*>(dst + 32 * j)      = u0;
                    *reinterpret_cast<uint4*>(dst + 32 * j + 16) = u1;
                }
                float e2 = e2p[pass];
                e2 += __shfl_xor_sync(0xffffffffu, e2, 1);
                e2 += __shfl_xor_sync(0xffffffffu, e2, 2);
                if (plq == 0) e2s[s * 64 + row] = e2;
            }

            bar_arriven(1 + s);   // stage s full
        }
    }
}

extern "C" void kernel_launch(void* const* d_in, const int* in_sizes, int n_in,
                              void* d_out, int out_size)
{
    const float* emb   = (const float*)d_in[0];
    const float* proto = (const float*)d_in[1];
    float* out = (float*)d_out;

    const long long nEmb   = (long long)in_sizes[0] / kD;
    const long long nTiles = (nEmb + kTM - 1) / kTM;

    cudaFuncSetAttribute(proto_kernel, cudaFuncAttributeMaxDynamicSharedMemorySize,
                         (int)SMEM_TOTAL);
    int dev = 0;
    cudaGetDevice(&dev);
    int nsm = 148;
    cudaDeviceGetAttribute(&nsm, cudaDevAttrMultiProcessorCount, dev);
    const int gridx = (int)((nTiles < (long long)nsm) ? nTiles : (long long)nsm);

    proto_kernel<<<gridx, kThreads, SMEM_TOTAL>>>(emb, proto, out, nEmb, nTiles);
}